// round 11
// baseline (speedup 1.0000x reference)
#include <cuda_runtime.h>
#include <cuda_fp16.h>
#include <cstdint>
#include <math.h>

// Problem constants
#define BATCH 1024
#define FDIM  128
#define EDIM  256
#define HEADS 8
#define DHEAD 32
#define MROWS (BATCH * FDIM)   // 131072
#define NCOLS (4 * EDIM)       // 1024 : [Q | K | V | R]

// ---------------------------------------------------------------------------
// Device scratch (no allocations allowed)
// ---------------------------------------------------------------------------
__device__ __half g_Ahi[(size_t)MROWS * EDIM];           // input hi
__device__ __half g_Alo[(size_t)MROWS * EDIM];           // input lo
__device__ __half g_Bh[(size_t)NCOLS * EDIM];            // [n][k] = W[k][n], fp16
__device__ __half g_Qhi[(size_t)MROWS * EDIM];           // proj outputs
__device__ __half g_Qlo[(size_t)MROWS * EDIM];
__device__ __half g_Khi[(size_t)MROWS * EDIM];
__device__ __half g_Vhi[(size_t)MROWS * EDIM];
__device__ float  g_R[(size_t)MROWS * EDIM];             // residual, fp32

// ---------------------------------------------------------------------------
// mma.sync m16n8k16 fp16 -> f32
// ---------------------------------------------------------------------------
__device__ __forceinline__ void mma16816(float* c, const uint32_t* a, const uint32_t* b) {
    asm volatile(
        "mma.sync.aligned.m16n8k16.row.col.f32.f16.f16.f32 "
        "{%0,%1,%2,%3}, {%4,%5,%6,%7}, {%8,%9}, {%0,%1,%2,%3};"
        : "+f"(c[0]), "+f"(c[1]), "+f"(c[2]), "+f"(c[3])
        : "r"(a[0]), "r"(a[1]), "r"(a[2]), "r"(a[3]), "r"(b[0]), "r"(b[1]));
}

__device__ __forceinline__ void split_half(float x, __half& h, __half& l) {
    h = __float2half_rn(x);
    l = __float2half_rn(x - __half2float(h));
}

__device__ __forceinline__ uint32_t pack2h(__half a, __half b) {
    __half2 t(a, b);   // a in low 16 bits (lower k index)
    return *(uint32_t*)&t;
}

__device__ __forceinline__ uint32_t smem_u32(const void* p) {
    uint32_t a;
    asm("{ .reg .u64 t; cvta.to.shared.u64 t, %1; cvt.u32.u64 %0, t; }" : "=r"(a) : "l"(p));
    return a;
}

__device__ __forceinline__ void cp16(uint32_t saddr, const void* gptr) {
    asm volatile("cp.async.cg.shared.global [%0], [%1], 16;" :: "r"(saddr), "l"(gptr));
}
#define CP_COMMIT() asm volatile("cp.async.commit_group;" ::: "memory")
#define CP_WAIT(N)  asm volatile("cp.async.wait_group %0;" :: "n"(N) : "memory")

// ---------------------------------------------------------------------------
// Conversion kernels
// ---------------------------------------------------------------------------
__global__ __launch_bounds__(256) void convert_A_kernel(const float* __restrict__ A) {
    size_t i = ((size_t)blockIdx.x * blockDim.x + threadIdx.x) * 4;
    if (i >= (size_t)MROWS * EDIM) return;
    float4 v = *(const float4*)&A[i];
    __half h0, l0, h1, l1, h2, l2, h3, l3;
    split_half(v.x, h0, l0); split_half(v.y, h1, l1);
    split_half(v.z, h2, l2); split_half(v.w, h3, l3);
    __half2* ph = (__half2*)&g_Ahi[i];
    __half2* pl = (__half2*)&g_Alo[i];
    ph[0] = __half2(h0, h1); ph[1] = __half2(h2, h3);
    pl[0] = __half2(l0, l1); pl[1] = __half2(l2, l3);
}

__global__ __launch_bounds__(256) void convert_W_kernel(
    const float* __restrict__ Wq, const float* __restrict__ Wk,
    const float* __restrict__ Wv, const float* __restrict__ Wr) {
    int id = blockIdx.x * blockDim.x + threadIdx.x;   // n*256 + k
    if (id >= NCOLS * EDIM) return;
    int n = id >> 8;
    int k = id & 255;
    const float* W = (n < 256) ? Wq : (n < 512) ? Wk : (n < 768) ? Wv : Wr;
    g_Bh[(size_t)n * EDIM + k] = __float2half_rn(W[(size_t)k * EDIM + (n & 255)]);
}

// ---------------------------------------------------------------------------
// Projection GEMM via mma.sync (split-fp16, 2 products), cp.async 2-stage.
// C[131072 x 1024] = A @ W.  CTA tile 128x128, warp tile 64x32, K chunks of 64.
// Epilogue routes by region: Q -> fp16 hi/lo, K/V -> fp16 hi, R -> fp32.
// ---------------------------------------------------------------------------
#define PSTR 72
#define PROJ_TILE (128 * PSTR * 2)           // 18432 B
#define PROJ_STAGE (3 * PROJ_TILE)           // 55296 B
#define PROJ_SMEM_BYTES (2 * PROJ_STAGE)     // 110592 B

__global__ __launch_bounds__(256, 2) void proj_mma_kernel() {
    extern __shared__ __half smh[];
    const uint32_t sbase = smem_u32(smh);

    const int tid = threadIdx.x;
    const int wid = tid >> 5;
    const int lane = tid & 31;
    const int m0 = blockIdx.y * 128;
    const int n0 = blockIdx.x * 128;
    const int wm = (wid & 1) * 64;
    const int wn = (wid >> 1) * 32;
    const int grp = lane >> 2;
    const int tig = lane & 3;

    float acc[4][4][4];
#pragma unroll
    for (int mf = 0; mf < 4; mf++)
#pragma unroll
        for (int nf = 0; nf < 4; nf++)
#pragma unroll
            for (int r = 0; r < 4; r++) acc[mf][nf][r] = 0.f;

    auto fill = [&](int c, int st) {
        const int k0 = c * 64;
        const uint32_t sa = sbase + st * PROJ_STAGE;
#pragma unroll
        for (int it = 0; it < 4; it++) {
            int idx = tid + it * 256;          // 0..1023
            int r = idx >> 3;
            int c16 = idx & 7;
            uint32_t off = (uint32_t)(r * PSTR + c16 * 8) * 2;
            size_t ga = (size_t)(m0 + r) * EDIM + k0 + c16 * 8;
            size_t gb = (size_t)(n0 + r) * EDIM + k0 + c16 * 8;
            cp16(sa + off, g_Ahi + ga);
            cp16(sa + PROJ_TILE + off, g_Alo + ga);
            cp16(sa + 2 * PROJ_TILE + off, g_Bh + gb);
        }
    };

    fill(0, 0); CP_COMMIT();
    fill(1, 1); CP_COMMIT();

    for (int c = 0; c < 4; c++) {
        if (c < 3) { CP_WAIT(1); } else { CP_WAIT(0); }
        __syncthreads();

        const int st = c & 1;
        const __half* sAh = smh + st * (PROJ_STAGE / 2);
        const __half* sAl = sAh + PROJ_TILE / 2;
        const __half* sB  = sAh + 2 * (PROJ_TILE / 2);

#pragma unroll
        for (int kk = 0; kk < 4; kk++) {
            const int kb = kk * 16 + tig * 2;
            uint32_t bh[4][2];
#pragma unroll
            for (int nf = 0; nf < 4; nf++) {
                int n = wn + nf * 8 + grp;
                bh[nf][0] = *(const uint32_t*)&sB[n * PSTR + kb];
                bh[nf][1] = *(const uint32_t*)&sB[n * PSTR + kb + 8];
            }
#pragma unroll
            for (int mf = 0; mf < 4; mf++) {
                int m = wm + mf * 16 + grp;
                uint32_t ah[4], al[4];
                ah[0] = *(const uint32_t*)&sAh[m * PSTR + kb];
                ah[1] = *(const uint32_t*)&sAh[(m + 8) * PSTR + kb];
                ah[2] = *(const uint32_t*)&sAh[m * PSTR + kb + 8];
                ah[3] = *(const uint32_t*)&sAh[(m + 8) * PSTR + kb + 8];
                al[0] = *(const uint32_t*)&sAl[m * PSTR + kb];
                al[1] = *(const uint32_t*)&sAl[(m + 8) * PSTR + kb];
                al[2] = *(const uint32_t*)&sAl[m * PSTR + kb + 8];
                al[3] = *(const uint32_t*)&sAl[(m + 8) * PSTR + kb + 8];
#pragma unroll
                for (int nf = 0; nf < 4; nf++) {
                    mma16816(acc[mf][nf], ah, bh[nf]);
                    mma16816(acc[mf][nf], al, bh[nf]);
                }
            }
        }
        __syncthreads();
        if (c + 2 < 4) { fill(c + 2, st); CP_COMMIT(); }
    }

    // Epilogue: region 0=Q (split hi/lo fp16), 1=K (fp16), 2=V (fp16), 3=R (fp32)
    const int region = blockIdx.x >> 1;
    const int nbase = (blockIdx.x & 1) * 128;

#pragma unroll
    for (int mf = 0; mf < 4; mf++) {
        size_t m = (size_t)(m0 + wm + mf * 16 + grp);
#pragma unroll
        for (int nf = 0; nf < 4; nf++) {
            int n = nbase + wn + nf * 8 + tig * 2;
            size_t i0 = m * EDIM + n;
            size_t i1 = (m + 8) * EDIM + n;
            float a0 = acc[mf][nf][0], a1 = acc[mf][nf][1];
            float a2 = acc[mf][nf][2], a3 = acc[mf][nf][3];
            if (region == 0) {
                __half h0, l0, h1, l1, h2, l2, h3, l3;
                split_half(a0, h0, l0); split_half(a1, h1, l1);
                split_half(a2, h2, l2); split_half(a3, h3, l3);
                *(__half2*)&g_Qhi[i0] = __half2(h0, h1);
                *(__half2*)&g_Qlo[i0] = __half2(l0, l1);
                *(__half2*)&g_Qhi[i1] = __half2(h2, h3);
                *(__half2*)&g_Qlo[i1] = __half2(l2, l3);
            } else if (region == 1) {
                *(__half2*)&g_Khi[i0] = __floats2half2_rn(a0, a1);
                *(__half2*)&g_Khi[i1] = __floats2half2_rn(a2, a3);
            } else if (region == 2) {
                *(__half2*)&g_Vhi[i0] = __floats2half2_rn(a0, a1);
                *(__half2*)&g_Vhi[i1] = __floats2half2_rn(a2, a3);
            } else {
                *(float2*)&g_R[i0] = make_float2(a0, a1);
                *(float2*)&g_R[i1] = make_float2(a2, a3);
            }
        }
    }
}

// ---------------------------------------------------------------------------
// Attention, register-resident S/P, split-fp16 2-product.
// Inputs are already fp16 (Q hi/lo, K hi, V hi) -> pure copies into smem.
// ---------------------------------------------------------------------------
#define QKSTR 40
#define VTSTR 136
#define AOFF_QH  0
#define AOFF_QL  (AOFF_QH + 128 * QKSTR * 2)     // 10240
#define AOFF_KH  (AOFF_QL + 128 * QKSTR * 2)     // 20480
#define AOFF_VTH (AOFF_KH + 128 * QKSTR * 2)     // 30720
#define ATT_SMEM_BYTES (AOFF_VTH + 32 * VTSTR * 2)  // 39424

__global__ __launch_bounds__(256, 2) void attn_mma_kernel(float* __restrict__ out)
{
    extern __shared__ char asm_[];
    __half* sQh  = (__half*)(asm_ + AOFF_QH);
    __half* sQl  = (__half*)(asm_ + AOFF_QL);
    __half* sKh  = (__half*)(asm_ + AOFF_KH);
    __half* sVth = (__half*)(asm_ + AOFF_VTH);

    const int bh = blockIdx.x;
    const int b = bh >> 3;
    const int h = bh & 7;
    const int tid = threadIdx.x;
    const int wid = tid >> 5;
    const int lane = tid & 31;
    const int grp = lane >> 2;
    const int tig = lane & 3;

    const size_t rowbase = (size_t)(b * FDIM) * EDIM;
    const int colQ = h * DHEAD;

    // ---- load fp16 tiles: 128 rows x 32 halves each (4 x 16B per row) ----
#pragma unroll
    for (int s = 0; s < 2; s++) {
        int idx = tid + s * 256;               // 0..511
        int r = idx >> 2;                      // 0..127
        int c8 = (idx & 3) * 8;                // 0,8,16,24
        size_t g = rowbase + (size_t)r * EDIM + colQ + c8;
        *(uint4*)&sQh[r * QKSTR + c8] = *(const uint4*)&g_Qhi[g];
        *(uint4*)&sQl[r * QKSTR + c8] = *(const uint4*)&g_Qlo[g];
        *(uint4*)&sKh[r * QKSTR + c8] = *(const uint4*)&g_Khi[g];
        // V transposed scatter
        const __half* vv = &g_Vhi[g];
#pragma unroll
        for (int j = 0; j < 8; j++)
            sVth[(c8 + j) * VTSTR + r] = vv[j];
    }
    __syncthreads();

    // ---- S = Q K^T : warp wid handles rows wm..wm+15, all 128 cols ----
    const int wm = wid * 16;
    float acc[16][4];
#pragma unroll
    for (int nf = 0; nf < 16; nf++)
#pragma unroll
        for (int r = 0; r < 4; r++) acc[nf][r] = 0.f;

#pragma unroll
    for (int kk = 0; kk < 2; kk++) {
        const int kb = kk * 16 + tig * 2;
        const int m = wm + grp;
        uint32_t ah[4], al[4];
        ah[0] = *(const uint32_t*)&sQh[m * QKSTR + kb];
        ah[1] = *(const uint32_t*)&sQh[(m + 8) * QKSTR + kb];
        ah[2] = *(const uint32_t*)&sQh[m * QKSTR + kb + 8];
        ah[3] = *(const uint32_t*)&sQh[(m + 8) * QKSTR + kb + 8];
        al[0] = *(const uint32_t*)&sQl[m * QKSTR + kb];
        al[1] = *(const uint32_t*)&sQl[(m + 8) * QKSTR + kb];
        al[2] = *(const uint32_t*)&sQl[m * QKSTR + kb + 8];
        al[3] = *(const uint32_t*)&sQl[(m + 8) * QKSTR + kb + 8];
#pragma unroll
        for (int nf = 0; nf < 16; nf++) {
            int n = nf * 8 + grp;
            uint32_t bhf[2];
            bhf[0] = *(const uint32_t*)&sKh[n * QKSTR + kb];
            bhf[1] = *(const uint32_t*)&sKh[n * QKSTR + kb + 8];
            mma16816(acc[nf], ah, bhf);
            mma16816(acc[nf], al, bhf);
        }
    }

    // ---- softmax in registers ----
    float mx0 = -1e30f, mx1 = -1e30f;
#pragma unroll
    for (int nf = 0; nf < 16; nf++) {
        mx0 = fmaxf(mx0, fmaxf(acc[nf][0], acc[nf][1]));
        mx1 = fmaxf(mx1, fmaxf(acc[nf][2], acc[nf][3]));
    }
#pragma unroll
    for (int o = 2; o >= 1; o >>= 1) {
        mx0 = fmaxf(mx0, __shfl_xor_sync(0xffffffffu, mx0, o));
        mx1 = fmaxf(mx1, __shfl_xor_sync(0xffffffffu, mx1, o));
    }
    float s0 = 0.f, s1 = 0.f;
#pragma unroll
    for (int nf = 0; nf < 16; nf++) {
        acc[nf][0] = __expf(acc[nf][0] - mx0);
        acc[nf][1] = __expf(acc[nf][1] - mx0);
        acc[nf][2] = __expf(acc[nf][2] - mx1);
        acc[nf][3] = __expf(acc[nf][3] - mx1);
        s0 += acc[nf][0] + acc[nf][1];
        s1 += acc[nf][2] + acc[nf][3];
    }
#pragma unroll
    for (int o = 2; o >= 1; o >>= 1) {
        s0 += __shfl_xor_sync(0xffffffffu, s0, o);
        s1 += __shfl_xor_sync(0xffffffffu, s1, o);
    }
    const float inv0 = 1.0f / s0;
    const float inv1 = 1.0f / s1;

    // ---- pack P into A-fragments (hi/lo), consuming acc ----
    uint32_t ph[8][4], pl[8][4];
#pragma unroll
    for (int j = 0; j < 8; j++) {
        float p00 = acc[2 * j][0] * inv0,     p01 = acc[2 * j][1] * inv0;
        float p02 = acc[2 * j][2] * inv1,     p03 = acc[2 * j][3] * inv1;
        float p10 = acc[2 * j + 1][0] * inv0, p11 = acc[2 * j + 1][1] * inv0;
        float p12 = acc[2 * j + 1][2] * inv1, p13 = acc[2 * j + 1][3] * inv1;
        __half ha, la, hb, lb;
        split_half(p00, ha, la); split_half(p01, hb, lb);
        ph[j][0] = pack2h(ha, hb); pl[j][0] = pack2h(la, lb);
        split_half(p02, ha, la); split_half(p03, hb, lb);
        ph[j][1] = pack2h(ha, hb); pl[j][1] = pack2h(la, lb);
        split_half(p10, ha, la); split_half(p11, hb, lb);
        ph[j][2] = pack2h(ha, hb); pl[j][2] = pack2h(la, lb);
        split_half(p12, ha, la); split_half(p13, hb, lb);
        ph[j][3] = pack2h(ha, hb); pl[j][3] = pack2h(la, lb);
    }

    // ---- O = P V : warp tile m16 x n32, k=128 (8 k16 blocks) ----
    float o[4][4];
#pragma unroll
    for (int nf = 0; nf < 4; nf++)
#pragma unroll
        for (int r = 0; r < 4; r++) o[nf][r] = 0.f;

#pragma unroll
    for (int kk = 0; kk < 8; kk++) {
        const int kb = kk * 16 + tig * 2;
#pragma unroll
        for (int nf = 0; nf < 4; nf++) {
            int n = nf * 8 + grp;
            uint32_t bhf[2];
            bhf[0] = *(const uint32_t*)&sVth[n * VTSTR + kb];
            bhf[1] = *(const uint32_t*)&sVth[n * VTSTR + kb + 8];
            mma16816(o[nf], ph[kk], bhf);
            mma16816(o[nf], pl[kk], bhf);
        }
    }

    // ---- epilogue: + residual, ReLU, store ----
    const size_t orowbase = (size_t)(b * FDIM);
#pragma unroll
    for (int nf = 0; nf < 4; nf++) {
        int cc = nf * 8 + tig * 2;
        int r0 = wm + grp;
        int r1 = r0 + 8;
        float2 rr0 = *(const float2*)&g_R[rowbase + (size_t)r0 * EDIM + colQ + cc];
        float2 rr1 = *(const float2*)&g_R[rowbase + (size_t)r1 * EDIM + colQ + cc];
        float2 o0, o1;
        o0.x = fmaxf(o[nf][0] + rr0.x, 0.f);
        o0.y = fmaxf(o[nf][1] + rr0.y, 0.f);
        o1.x = fmaxf(o[nf][2] + rr1.x, 0.f);
        o1.y = fmaxf(o[nf][3] + rr1.y, 0.f);
        *(float2*)&out[(orowbase + r0) * EDIM + colQ + cc] = o0;
        *(float2*)&out[(orowbase + r1) * EDIM + colQ + cc] = o1;
    }
}

// ---------------------------------------------------------------------------
// Launch
// ---------------------------------------------------------------------------
extern "C" void kernel_launch(void* const* d_in, const int* in_sizes, int n_in,
                              void* d_out, int out_size)
{
    const float* inputs = (const float*)d_in[0];
    const float* Wq     = (const float*)d_in[1];
    const float* Wk     = (const float*)d_in[2];
    const float* Wv     = (const float*)d_in[3];
    const float* Wr     = (const float*)d_in[4];
    float* out = (float*)d_out;

    cudaFuncSetAttribute(proj_mma_kernel, cudaFuncAttributeMaxDynamicSharedMemorySize,
                         PROJ_SMEM_BYTES);
    cudaFuncSetAttribute(attn_mma_kernel, cudaFuncAttributeMaxDynamicSharedMemorySize,
                         ATT_SMEM_BYTES);

    convert_A_kernel<<<(MROWS * EDIM / 4 + 255) / 256, 256>>>(inputs);
    convert_W_kernel<<<(NCOLS * EDIM + 255) / 256, 256>>>(Wq, Wk, Wv, Wr);

    dim3 gridP(NCOLS / 128, MROWS / 128);   // 8 x 1024
    proj_mma_kernel<<<gridP, 256, PROJ_SMEM_BYTES>>>();

    attn_mma_kernel<<<BATCH * HEADS, 256, ATT_SMEM_BYTES>>>(out);
}

// round 12
// speedup vs baseline: 1.1041x; 1.1041x over previous
#include <cuda_runtime.h>
#include <cuda_fp16.h>
#include <cstdint>
#include <math.h>

// Problem constants
#define BATCH 1024
#define FDIM  128
#define EDIM  256
#define HEADS 8
#define DHEAD 32
#define MROWS (BATCH * FDIM)   // 131072
#define NCOLS (4 * EDIM)       // 1024 : [Q | K | V | R]

// ---------------------------------------------------------------------------
// Device scratch (no allocations allowed)
// ---------------------------------------------------------------------------
__device__ float g_qkvr[(size_t)MROWS * NCOLS];          // 537 MB fp32 Q|K|V|R
__device__ __half g_Ahi[(size_t)MROWS * EDIM];           // input hi
__device__ __half g_Alo[(size_t)MROWS * EDIM];           // input lo
__device__ __half g_Bh[(size_t)NCOLS * EDIM];            // [n][k] = W[k][n], fp16

// ---------------------------------------------------------------------------
// mma.sync m16n8k16 fp16 -> f32
// ---------------------------------------------------------------------------
__device__ __forceinline__ void mma16816(float* c, const uint32_t* a, const uint32_t* b) {
    asm volatile(
        "mma.sync.aligned.m16n8k16.row.col.f32.f16.f16.f32 "
        "{%0,%1,%2,%3}, {%4,%5,%6,%7}, {%8,%9}, {%0,%1,%2,%3};"
        : "+f"(c[0]), "+f"(c[1]), "+f"(c[2]), "+f"(c[3])
        : "r"(a[0]), "r"(a[1]), "r"(a[2]), "r"(a[3]), "r"(b[0]), "r"(b[1]));
}

__device__ __forceinline__ void split_half(float x, __half& h, __half& l) {
    h = __float2half_rn(x);
    l = __float2half_rn(x - __half2float(h));
}

__device__ __forceinline__ uint32_t pack2h(__half a, __half b) {
    __half2 t(a, b);   // a in low 16 bits (lower k index)
    return *(uint32_t*)&t;
}

__device__ __forceinline__ uint32_t smem_u32(const void* p) {
    uint32_t a;
    asm("{ .reg .u64 t; cvta.to.shared.u64 t, %1; cvt.u32.u64 %0, t; }" : "=r"(a) : "l"(p));
    return a;
}

__device__ __forceinline__ void cp16(uint32_t saddr, const void* gptr) {
    asm volatile("cp.async.cg.shared.global [%0], [%1], 16;" :: "r"(saddr), "l"(gptr));
}
#define CP_COMMIT() asm volatile("cp.async.commit_group;" ::: "memory")
#define CP_WAIT(N)  asm volatile("cp.async.wait_group %0;" :: "n"(N) : "memory")

// ---------------------------------------------------------------------------
// Conversion kernels
// ---------------------------------------------------------------------------
__global__ __launch_bounds__(256) void convert_A_kernel(const float* __restrict__ A) {
    size_t i = ((size_t)blockIdx.x * blockDim.x + threadIdx.x) * 4;
    if (i >= (size_t)MROWS * EDIM) return;
    float4 v = *(const float4*)&A[i];
    __half h0, l0, h1, l1, h2, l2, h3, l3;
    split_half(v.x, h0, l0); split_half(v.y, h1, l1);
    split_half(v.z, h2, l2); split_half(v.w, h3, l3);
    __half2* ph = (__half2*)&g_Ahi[i];
    __half2* pl = (__half2*)&g_Alo[i];
    ph[0] = __half2(h0, h1); ph[1] = __half2(h2, h3);
    pl[0] = __half2(l0, l1); pl[1] = __half2(l2, l3);
}

__global__ __launch_bounds__(256) void convert_W_kernel(
    const float* __restrict__ Wq, const float* __restrict__ Wk,
    const float* __restrict__ Wv, const float* __restrict__ Wr) {
    int id = blockIdx.x * blockDim.x + threadIdx.x;   // n*256 + k
    if (id >= NCOLS * EDIM) return;
    int n = id >> 8;
    int k = id & 255;
    const float* W = (n < 256) ? Wq : (n < 512) ? Wk : (n < 768) ? Wv : Wr;
    g_Bh[(size_t)n * EDIM + k] = __float2half_rn(W[(size_t)k * EDIM + (n & 255)]);
}

// ---------------------------------------------------------------------------
// Projection GEMM via mma.sync, cp.async 2-stage.
// Q,K regions (blockIdx.x < 4): split-fp16 2 products.
// V,R regions (blockIdx.x >= 4): single product (Ah*Bh) — precision analysis
// shows those paths tolerate fp16 input rounding (~2e-4, quadrature-safe).
// ---------------------------------------------------------------------------
#define PSTR 72
#define PROJ_TILE (128 * PSTR * 2)           // 18432 B
#define PROJ_STAGE (3 * PROJ_TILE)           // 55296 B
#define PROJ_SMEM_BYTES (2 * PROJ_STAGE)     // 110592 B

__global__ __launch_bounds__(256, 2) void proj_mma_kernel() {
    extern __shared__ __half smh[];
    const uint32_t sbase = smem_u32(smh);

    const int tid = threadIdx.x;
    const int wid = tid >> 5;
    const int lane = tid & 31;
    const int m0 = blockIdx.y * 128;
    const int n0 = blockIdx.x * 128;
    const bool twoProd = (blockIdx.x < 4);   // Q,K regions
    const int wm = (wid & 1) * 64;
    const int wn = (wid >> 1) * 32;
    const int grp = lane >> 2;
    const int tig = lane & 3;

    float acc[4][4][4];
#pragma unroll
    for (int mf = 0; mf < 4; mf++)
#pragma unroll
        for (int nf = 0; nf < 4; nf++)
#pragma unroll
            for (int r = 0; r < 4; r++) acc[mf][nf][r] = 0.f;

    auto fill = [&](int c, int st) {
        const int k0 = c * 64;
        const uint32_t sa = sbase + st * PROJ_STAGE;
#pragma unroll
        for (int it = 0; it < 4; it++) {
            int idx = tid + it * 256;          // 0..1023
            int r = idx >> 3;
            int c16 = idx & 7;
            uint32_t off = (uint32_t)(r * PSTR + c16 * 8) * 2;
            size_t ga = (size_t)(m0 + r) * EDIM + k0 + c16 * 8;
            size_t gb = (size_t)(n0 + r) * EDIM + k0 + c16 * 8;
            cp16(sa + off, g_Ahi + ga);
            if (twoProd) cp16(sa + PROJ_TILE + off, g_Alo + ga);
            cp16(sa + 2 * PROJ_TILE + off, g_Bh + gb);
        }
    };

    fill(0, 0); CP_COMMIT();
    fill(1, 1); CP_COMMIT();

    for (int c = 0; c < 4; c++) {
        if (c < 3) { CP_WAIT(1); } else { CP_WAIT(0); }
        __syncthreads();

        const int st = c & 1;
        const __half* sAh = smh + st * (PROJ_STAGE / 2);
        const __half* sAl = sAh + PROJ_TILE / 2;
        const __half* sB  = sAh + 2 * (PROJ_TILE / 2);

#pragma unroll
        for (int kk = 0; kk < 4; kk++) {
            const int kb = kk * 16 + tig * 2;
            uint32_t bh[4][2];
#pragma unroll
            for (int nf = 0; nf < 4; nf++) {
                int n = wn + nf * 8 + grp;
                bh[nf][0] = *(const uint32_t*)&sB[n * PSTR + kb];
                bh[nf][1] = *(const uint32_t*)&sB[n * PSTR + kb + 8];
            }
#pragma unroll
            for (int mf = 0; mf < 4; mf++) {
                int m = wm + mf * 16 + grp;
                uint32_t ah[4], al[4];
                ah[0] = *(const uint32_t*)&sAh[m * PSTR + kb];
                ah[1] = *(const uint32_t*)&sAh[(m + 8) * PSTR + kb];
                ah[2] = *(const uint32_t*)&sAh[m * PSTR + kb + 8];
                ah[3] = *(const uint32_t*)&sAh[(m + 8) * PSTR + kb + 8];
                if (twoProd) {
                    al[0] = *(const uint32_t*)&sAl[m * PSTR + kb];
                    al[1] = *(const uint32_t*)&sAl[(m + 8) * PSTR + kb];
                    al[2] = *(const uint32_t*)&sAl[m * PSTR + kb + 8];
                    al[3] = *(const uint32_t*)&sAl[(m + 8) * PSTR + kb + 8];
                }
#pragma unroll
                for (int nf = 0; nf < 4; nf++) {
                    mma16816(acc[mf][nf], ah, bh[nf]);
                    if (twoProd) mma16816(acc[mf][nf], al, bh[nf]);
                }
            }
        }
        __syncthreads();
        if (c + 2 < 4) { fill(c + 2, st); CP_COMMIT(); }
    }

#pragma unroll
    for (int mf = 0; mf < 4; mf++) {
        int m = m0 + wm + mf * 16 + grp;
#pragma unroll
        for (int nf = 0; nf < 4; nf++) {
            int n = n0 + wn + nf * 8 + tig * 2;
            *(float2*)&g_qkvr[(size_t)m * NCOLS + n] = make_float2(acc[mf][nf][0], acc[mf][nf][1]);
            *(float2*)&g_qkvr[(size_t)(m + 8) * NCOLS + n] = make_float2(acc[mf][nf][2], acc[mf][nf][3]);
        }
    }
}

// ---------------------------------------------------------------------------
// Attention, register-resident S/P, split-fp16 2-product (R10-identical).
// ---------------------------------------------------------------------------
#define QKSTR 40
#define VTSTR 136
#define AOFF_QH  0
#define AOFF_QL  (AOFF_QH + 128 * QKSTR * 2)     // 10240
#define AOFF_KH  (AOFF_QL + 128 * QKSTR * 2)     // 20480
#define AOFF_VTH (AOFF_KH + 128 * QKSTR * 2)     // 30720
#define ATT_SMEM_BYTES (AOFF_VTH + 32 * VTSTR * 2)  // 39424

__global__ __launch_bounds__(256, 2) void attn_mma_kernel(float* __restrict__ out)
{
    extern __shared__ char asm_[];
    __half* sQh  = (__half*)(asm_ + AOFF_QH);
    __half* sQl  = (__half*)(asm_ + AOFF_QL);
    __half* sKh  = (__half*)(asm_ + AOFF_KH);
    __half* sVth = (__half*)(asm_ + AOFF_VTH);

    const int bh = blockIdx.x;
    const int b = bh >> 3;
    const int h = bh & 7;
    const int tid = threadIdx.x;
    const int wid = tid >> 5;
    const int lane = tid & 31;
    const int grp = lane >> 2;
    const int tig = lane & 3;

    const size_t rowbase = (size_t)(b * FDIM) * NCOLS;
    const int colQ = h * DHEAD;

    // ---- load Q,K,V (fp32) -> fp16 smem tiles; Q split, V transposed ----
#pragma unroll
    for (int s = 0; s < 4; s++) {
        int idx = tid + s * 256;               // 0..1023
        int r = idx >> 3;                      // 0..127
        int c4 = (idx & 7) * 4;                // 0..28
        const float* src = &g_qkvr[rowbase + (size_t)r * NCOLS + colQ + c4];
        float4 q = *(const float4*)(src);
        float4 k = *(const float4*)(src + 256);
        float4 v = *(const float4*)(src + 512);
        __half h0, l0, h1, l1, h2, l2, h3, l3;
        split_half(q.x, h0, l0); split_half(q.y, h1, l1);
        split_half(q.z, h2, l2); split_half(q.w, h3, l3);
        *(__half2*)&sQh[r * QKSTR + c4]     = __half2(h0, h1);
        *(__half2*)&sQh[r * QKSTR + c4 + 2] = __half2(h2, h3);
        *(__half2*)&sQl[r * QKSTR + c4]     = __half2(l0, l1);
        *(__half2*)&sQl[r * QKSTR + c4 + 2] = __half2(l2, l3);
        *(__half2*)&sKh[r * QKSTR + c4]     = __half2(__float2half_rn(k.x), __float2half_rn(k.y));
        *(__half2*)&sKh[r * QKSTR + c4 + 2] = __half2(__float2half_rn(k.z), __float2half_rn(k.w));
        sVth[(c4 + 0) * VTSTR + r] = __float2half_rn(v.x);
        sVth[(c4 + 1) * VTSTR + r] = __float2half_rn(v.y);
        sVth[(c4 + 2) * VTSTR + r] = __float2half_rn(v.z);
        sVth[(c4 + 3) * VTSTR + r] = __float2half_rn(v.w);
    }
    __syncthreads();

    // ---- S = Q K^T : warp wid handles rows wm..wm+15, all 128 cols ----
    const int wm = wid * 16;
    float acc[16][4];
#pragma unroll
    for (int nf = 0; nf < 16; nf++)
#pragma unroll
        for (int r = 0; r < 4; r++) acc[nf][r] = 0.f;

#pragma unroll
    for (int kk = 0; kk < 2; kk++) {
        const int kb = kk * 16 + tig * 2;
        const int m = wm + grp;
        uint32_t ah[4], al[4];
        ah[0] = *(const uint32_t*)&sQh[m * QKSTR + kb];
        ah[1] = *(const uint32_t*)&sQh[(m + 8) * QKSTR + kb];
        ah[2] = *(const uint32_t*)&sQh[m * QKSTR + kb + 8];
        ah[3] = *(const uint32_t*)&sQh[(m + 8) * QKSTR + kb + 8];
        al[0] = *(const uint32_t*)&sQl[m * QKSTR + kb];
        al[1] = *(const uint32_t*)&sQl[(m + 8) * QKSTR + kb];
        al[2] = *(const uint32_t*)&sQl[m * QKSTR + kb + 8];
        al[3] = *(const uint32_t*)&sQl[(m + 8) * QKSTR + kb + 8];
#pragma unroll
        for (int nf = 0; nf < 16; nf++) {
            int n = nf * 8 + grp;
            uint32_t bhf[2];
            bhf[0] = *(const uint32_t*)&sKh[n * QKSTR + kb];
            bhf[1] = *(const uint32_t*)&sKh[n * QKSTR + kb + 8];
            mma16816(acc[nf], ah, bhf);
            mma16816(acc[nf], al, bhf);
        }
    }

    // ---- softmax in registers ----
    float mx0 = -1e30f, mx1 = -1e30f;
#pragma unroll
    for (int nf = 0; nf < 16; nf++) {
        mx0 = fmaxf(mx0, fmaxf(acc[nf][0], acc[nf][1]));
        mx1 = fmaxf(mx1, fmaxf(acc[nf][2], acc[nf][3]));
    }
#pragma unroll
    for (int o = 2; o >= 1; o >>= 1) {
        mx0 = fmaxf(mx0, __shfl_xor_sync(0xffffffffu, mx0, o));
        mx1 = fmaxf(mx1, __shfl_xor_sync(0xffffffffu, mx1, o));
    }
    float s0 = 0.f, s1 = 0.f;
#pragma unroll
    for (int nf = 0; nf < 16; nf++) {
        acc[nf][0] = __expf(acc[nf][0] - mx0);
        acc[nf][1] = __expf(acc[nf][1] - mx0);
        acc[nf][2] = __expf(acc[nf][2] - mx1);
        acc[nf][3] = __expf(acc[nf][3] - mx1);
        s0 += acc[nf][0] + acc[nf][1];
        s1 += acc[nf][2] + acc[nf][3];
    }
#pragma unroll
    for (int o = 2; o >= 1; o >>= 1) {
        s0 += __shfl_xor_sync(0xffffffffu, s0, o);
        s1 += __shfl_xor_sync(0xffffffffu, s1, o);
    }
    const float inv0 = 1.0f / s0;
    const float inv1 = 1.0f / s1;

    // ---- pack P into A-fragments (hi/lo), consuming acc ----
    uint32_t ph[8][4], pl[8][4];
#pragma unroll
    for (int j = 0; j < 8; j++) {
        float p00 = acc[2 * j][0] * inv0,     p01 = acc[2 * j][1] * inv0;
        float p02 = acc[2 * j][2] * inv1,     p03 = acc[2 * j][3] * inv1;
        float p10 = acc[2 * j + 1][0] * inv0, p11 = acc[2 * j + 1][1] * inv0;
        float p12 = acc[2 * j + 1][2] * inv1, p13 = acc[2 * j + 1][3] * inv1;
        __half ha, la, hb, lb;
        split_half(p00, ha, la); split_half(p01, hb, lb);
        ph[j][0] = pack2h(ha, hb); pl[j][0] = pack2h(la, lb);
        split_half(p02, ha, la); split_half(p03, hb, lb);
        ph[j][1] = pack2h(ha, hb); pl[j][1] = pack2h(la, lb);
        split_half(p10, ha, la); split_half(p11, hb, lb);
        ph[j][2] = pack2h(ha, hb); pl[j][2] = pack2h(la, lb);
        split_half(p12, ha, la); split_half(p13, hb, lb);
        ph[j][3] = pack2h(ha, hb); pl[j][3] = pack2h(la, lb);
    }

    // ---- O = P V : warp tile m16 x n32, k=128 (8 k16 blocks) ----
    float o[4][4];
#pragma unroll
    for (int nf = 0; nf < 4; nf++)
#pragma unroll
        for (int r = 0; r < 4; r++) o[nf][r] = 0.f;

#pragma unroll
    for (int kk = 0; kk < 8; kk++) {
        const int kb = kk * 16 + tig * 2;
#pragma unroll
        for (int nf = 0; nf < 4; nf++) {
            int n = nf * 8 + grp;
            uint32_t bhf[2];
            bhf[0] = *(const uint32_t*)&sVth[n * VTSTR + kb];
            bhf[1] = *(const uint32_t*)&sVth[n * VTSTR + kb + 8];
            mma16816(o[nf], ph[kk], bhf);
            mma16816(o[nf], pl[kk], bhf);
        }
    }

    // ---- epilogue: + residual, ReLU, store ----
    const size_t orowbase = (size_t)(b * FDIM);
#pragma unroll
    for (int nf = 0; nf < 4; nf++) {
        int cc = nf * 8 + tig * 2;
        int r0 = wm + grp;
        int r1 = r0 + 8;
        float2 rr0 = *(const float2*)&g_qkvr[rowbase + (size_t)r0 * NCOLS + 768 + colQ + cc];
        float2 rr1 = *(const float2*)&g_qkvr[rowbase + (size_t)r1 * NCOLS + 768 + colQ + cc];
        float2 o0, o1;
        o0.x = fmaxf(o[nf][0] + rr0.x, 0.f);
        o0.y = fmaxf(o[nf][1] + rr0.y, 0.f);
        o1.x = fmaxf(o[nf][2] + rr1.x, 0.f);
        o1.y = fmaxf(o[nf][3] + rr1.y, 0.f);
        *(float2*)&out[(orowbase + r0) * EDIM + colQ + cc] = o0;
        *(float2*)&out[(orowbase + r1) * EDIM + colQ + cc] = o1;
    }
}

// ---------------------------------------------------------------------------
// Launch
// ---------------------------------------------------------------------------
extern "C" void kernel_launch(void* const* d_in, const int* in_sizes, int n_in,
                              void* d_out, int out_size)
{
    const float* inputs = (const float*)d_in[0];
    const float* Wq     = (const float*)d_in[1];
    const float* Wk     = (const float*)d_in[2];
    const float* Wv     = (const float*)d_in[3];
    const float* Wr     = (const float*)d_in[4];
    float* out = (float*)d_out;

    cudaFuncSetAttribute(proj_mma_kernel, cudaFuncAttributeMaxDynamicSharedMemorySize,
                         PROJ_SMEM_BYTES);
    cudaFuncSetAttribute(attn_mma_kernel, cudaFuncAttributeMaxDynamicSharedMemorySize,
                         ATT_SMEM_BYTES);

    convert_A_kernel<<<(MROWS * EDIM / 4 + 255) / 256, 256>>>(inputs);
    convert_W_kernel<<<(NCOLS * EDIM + 255) / 256, 256>>>(Wq, Wk, Wv, Wr);

    dim3 gridP(NCOLS / 128, MROWS / 128);   // 8 x 1024
    proj_mma_kernel<<<gridP, 256, PROJ_SMEM_BYTES>>>();

    attn_mma_kernel<<<BATCH * HEADS, 256, ATT_SMEM_BYTES>>>(out);
}

// round 13
// speedup vs baseline: 1.1677x; 1.0577x over previous
#include <cuda_runtime.h>
#include <cuda_fp16.h>
#include <cstdint>
#include <math.h>

// Problem constants
#define BATCH 1024
#define FDIM  128
#define EDIM  256
#define HEADS 8
#define DHEAD 32
#define MROWS (BATCH * FDIM)   // 131072
#define NCOLS (4 * EDIM)       // 1024 : [Q | K | V | R]

// ---------------------------------------------------------------------------
// Device scratch (no allocations allowed)
// ---------------------------------------------------------------------------
__device__ float g_qkvr[(size_t)MROWS * NCOLS];          // 537 MB fp32 Q|K|V|R
__device__ __half g_Ahi[(size_t)MROWS * EDIM];           // input hi
__device__ __half g_Alo[(size_t)MROWS * EDIM];           // input lo
__device__ __half g_Bh[(size_t)NCOLS * EDIM];            // [n][k] = W[k][n], fp16

// ---------------------------------------------------------------------------
// mma.sync m16n8k16 fp16 -> f32 ; ldmatrix fragment loads
// ---------------------------------------------------------------------------
__device__ __forceinline__ void mma16816(float* c, const uint32_t* a, const uint32_t* b) {
    asm volatile(
        "mma.sync.aligned.m16n8k16.row.col.f32.f16.f16.f32 "
        "{%0,%1,%2,%3}, {%4,%5,%6,%7}, {%8,%9}, {%0,%1,%2,%3};"
        : "+f"(c[0]), "+f"(c[1]), "+f"(c[2]), "+f"(c[3])
        : "r"(a[0]), "r"(a[1]), "r"(a[2]), "r"(a[3]), "r"(b[0]), "r"(b[1]));
}

__device__ __forceinline__ void ldsm_x4(uint32_t* r, uint32_t saddr) {
    asm volatile("ldmatrix.sync.aligned.m8n8.x4.shared.b16 {%0,%1,%2,%3}, [%4];"
                 : "=r"(r[0]), "=r"(r[1]), "=r"(r[2]), "=r"(r[3]) : "r"(saddr));
}

__device__ __forceinline__ void split_half(float x, __half& h, __half& l) {
    h = __float2half_rn(x);
    l = __float2half_rn(x - __half2float(h));
}

__device__ __forceinline__ uint32_t pack2h(__half a, __half b) {
    __half2 t(a, b);
    return *(uint32_t*)&t;
}

__device__ __forceinline__ uint32_t smem_u32(const void* p) {
    uint32_t a;
    asm("{ .reg .u64 t; cvta.to.shared.u64 t, %1; cvt.u32.u64 %0, t; }" : "=r"(a) : "l"(p));
    return a;
}

__device__ __forceinline__ void cp16(uint32_t saddr, const void* gptr) {
    asm volatile("cp.async.cg.shared.global [%0], [%1], 16;" :: "r"(saddr), "l"(gptr));
}
#define CP_COMMIT() asm volatile("cp.async.commit_group;" ::: "memory")
#define CP_WAIT(N)  asm volatile("cp.async.wait_group %0;" :: "n"(N) : "memory")

// ---------------------------------------------------------------------------
// Conversion kernels
// ---------------------------------------------------------------------------
__global__ __launch_bounds__(256) void convert_A_kernel(const float* __restrict__ A) {
    size_t i = ((size_t)blockIdx.x * blockDim.x + threadIdx.x) * 4;
    if (i >= (size_t)MROWS * EDIM) return;
    float4 v = *(const float4*)&A[i];
    __half h0, l0, h1, l1, h2, l2, h3, l3;
    split_half(v.x, h0, l0); split_half(v.y, h1, l1);
    split_half(v.z, h2, l2); split_half(v.w, h3, l3);
    __half2* ph = (__half2*)&g_Ahi[i];
    __half2* pl = (__half2*)&g_Alo[i];
    ph[0] = __half2(h0, h1); ph[1] = __half2(h2, h3);
    pl[0] = __half2(l0, l1); pl[1] = __half2(l2, l3);
}

__global__ __launch_bounds__(256) void convert_W_kernel(
    const float* __restrict__ Wq, const float* __restrict__ Wk,
    const float* __restrict__ Wv, const float* __restrict__ Wr) {
    int id = blockIdx.x * blockDim.x + threadIdx.x;   // n*256 + k
    if (id >= NCOLS * EDIM) return;
    int n = id >> 8;
    int k = id & 255;
    const float* W = (n < 256) ? Wq : (n < 512) ? Wk : (n < 768) ? Wv : Wr;
    g_Bh[(size_t)n * EDIM + k] = __float2half_rn(W[(size_t)k * EDIM + (n & 255)]);
}

// ---------------------------------------------------------------------------
// Projection GEMM via mma.sync + ldmatrix, cp.async 2-stage.
// Q,K (blockIdx.x < 4): split-fp16 2 products; V,R: single product.
// ---------------------------------------------------------------------------
#define PSTR 72
#define PROJ_TILE (128 * PSTR * 2)           // 18432 B
#define PROJ_STAGE (3 * PROJ_TILE)           // 55296 B
#define PROJ_SMEM_BYTES (2 * PROJ_STAGE)     // 110592 B

__global__ __launch_bounds__(256, 2) void proj_mma_kernel() {
    extern __shared__ __half smh[];
    const uint32_t sbase = smem_u32(smh);

    const int tid = threadIdx.x;
    const int wid = tid >> 5;
    const int lane = tid & 31;
    const int m0 = blockIdx.y * 128;
    const int n0 = blockIdx.x * 128;
    const bool twoProd = (blockIdx.x < 4);   // Q,K regions
    const int wm = (wid & 1) * 64;
    const int wn = (wid >> 1) * 32;
    const int grp = lane >> 2;
    const int tig = lane & 3;

    // ldmatrix per-lane address components
    const int a_row = lane & 15;             // A: rows m..m+15
    const int a_col = (lane >> 4) * 8;       // k or k+8
    const int b_row = lane & 7;              // B: 8 n-rows per matrix
    const int b_col = ((lane >> 3) & 1) * 8; // k or k+8
    const int b_nf  = lane >> 4;             // which n8-frag within the pair

    float acc[4][4][4];
#pragma unroll
    for (int mf = 0; mf < 4; mf++)
#pragma unroll
        for (int nf = 0; nf < 4; nf++)
#pragma unroll
            for (int r = 0; r < 4; r++) acc[mf][nf][r] = 0.f;

    auto fill = [&](int c, int st) {
        const int k0 = c * 64;
        const uint32_t sa = sbase + st * PROJ_STAGE;
#pragma unroll
        for (int it = 0; it < 4; it++) {
            int idx = tid + it * 256;          // 0..1023
            int r = idx >> 3;
            int c16 = idx & 7;
            uint32_t off = (uint32_t)(r * PSTR + c16 * 8) * 2;
            size_t ga = (size_t)(m0 + r) * EDIM + k0 + c16 * 8;
            size_t gb = (size_t)(n0 + r) * EDIM + k0 + c16 * 8;
            cp16(sa + off, g_Ahi + ga);
            if (twoProd) cp16(sa + PROJ_TILE + off, g_Alo + ga);
            cp16(sa + 2 * PROJ_TILE + off, g_Bh + gb);
        }
    };

    fill(0, 0); CP_COMMIT();
    fill(1, 1); CP_COMMIT();

    for (int c = 0; c < 4; c++) {
        if (c < 3) { CP_WAIT(1); } else { CP_WAIT(0); }
        __syncthreads();

        const int st = c & 1;
        const uint32_t sAh = sbase + st * PROJ_STAGE;
        const uint32_t sAl = sAh + PROJ_TILE;
        const uint32_t sB  = sAh + 2 * PROJ_TILE;

#pragma unroll
        for (int kk = 0; kk < 4; kk++) {
            const int kb0 = kk * 16;
            // B fragments: two x4 covering nf 0..3
            uint32_t b01[4], b23[4];
            ldsm_x4(b01, sB + (uint32_t)(((wn + b_nf * 8 + b_row) * PSTR) + kb0 + b_col) * 2);
            ldsm_x4(b23, sB + (uint32_t)(((wn + (2 + b_nf) * 8 + b_row) * PSTR) + kb0 + b_col) * 2);
#pragma unroll
            for (int mf = 0; mf < 4; mf++) {
                const uint32_t aoff = (uint32_t)(((wm + mf * 16 + a_row) * PSTR) + kb0 + a_col) * 2;
                uint32_t ah[4], al[4];
                ldsm_x4(ah, sAh + aoff);
                if (twoProd) ldsm_x4(al, sAl + aoff);
#pragma unroll
                for (int nf = 0; nf < 4; nf++) {
                    const uint32_t* bp = (nf < 2) ? (b01 + (nf & 1) * 2) : (b23 + (nf & 1) * 2);
                    mma16816(acc[mf][nf], ah, bp);
                    if (twoProd) mma16816(acc[mf][nf], al, bp);
                }
            }
        }
        __syncthreads();
        if (c + 2 < 4) { fill(c + 2, st); CP_COMMIT(); }
    }

#pragma unroll
    for (int mf = 0; mf < 4; mf++) {
        int m = m0 + wm + mf * 16 + grp;
#pragma unroll
        for (int nf = 0; nf < 4; nf++) {
            int n = n0 + wn + nf * 8 + tig * 2;
            *(float2*)&g_qkvr[(size_t)m * NCOLS + n] = make_float2(acc[mf][nf][0], acc[mf][nf][1]);
            *(float2*)&g_qkvr[(size_t)(m + 8) * NCOLS + n] = make_float2(acc[mf][nf][2], acc[mf][nf][3]);
        }
    }
}

// ---------------------------------------------------------------------------
// Attention, register-resident S/P, split-fp16 2-product, ldmatrix loads.
// ---------------------------------------------------------------------------
#define QKSTR 40
#define VTSTR 136
#define AOFF_QH  0
#define AOFF_QL  (AOFF_QH + 128 * QKSTR * 2)     // 10240
#define AOFF_KH  (AOFF_QL + 128 * QKSTR * 2)     // 20480
#define AOFF_VTH (AOFF_KH + 128 * QKSTR * 2)     // 30720
#define ATT_SMEM_BYTES (AOFF_VTH + 32 * VTSTR * 2)  // 39424

__global__ __launch_bounds__(256, 2) void attn_mma_kernel(float* __restrict__ out)
{
    extern __shared__ char asm_[];
    __half* sQhp = (__half*)(asm_ + AOFF_QH);
    __half* sQlp = (__half*)(asm_ + AOFF_QL);
    __half* sKhp = (__half*)(asm_ + AOFF_KH);
    __half* sVtp = (__half*)(asm_ + AOFF_VTH);
    const uint32_t sQh = smem_u32(sQhp);
    const uint32_t sQl = smem_u32(sQlp);
    const uint32_t sKh = smem_u32(sKhp);
    const uint32_t sVt = smem_u32(sVtp);

    const int bh = blockIdx.x;
    const int b = bh >> 3;
    const int h = bh & 7;
    const int tid = threadIdx.x;
    const int wid = tid >> 5;
    const int lane = tid & 31;
    const int grp = lane >> 2;
    const int tig = lane & 3;

    const int a_row = lane & 15;
    const int a_col = (lane >> 4) * 8;
    const int b_row = lane & 7;
    const int b_col = ((lane >> 3) & 1) * 8;
    const int b_nf  = lane >> 4;

    const size_t rowbase = (size_t)(b * FDIM) * NCOLS;
    const int colQ = h * DHEAD;

    // ---- load Q,K,V (fp32) -> fp16 smem tiles; Q split, V transposed ----
#pragma unroll
    for (int s = 0; s < 4; s++) {
        int idx = tid + s * 256;               // 0..1023
        int r = idx >> 3;                      // 0..127
        int c4 = (idx & 7) * 4;                // 0..28
        const float* src = &g_qkvr[rowbase + (size_t)r * NCOLS + colQ + c4];
        float4 q = *(const float4*)(src);
        float4 k = *(const float4*)(src + 256);
        float4 v = *(const float4*)(src + 512);
        __half h0, l0, h1, l1, h2, l2, h3, l3;
        split_half(q.x, h0, l0); split_half(q.y, h1, l1);
        split_half(q.z, h2, l2); split_half(q.w, h3, l3);
        *(__half2*)&sQhp[r * QKSTR + c4]     = __half2(h0, h1);
        *(__half2*)&sQhp[r * QKSTR + c4 + 2] = __half2(h2, h3);
        *(__half2*)&sQlp[r * QKSTR + c4]     = __half2(l0, l1);
        *(__half2*)&sQlp[r * QKSTR + c4 + 2] = __half2(l2, l3);
        *(__half2*)&sKhp[r * QKSTR + c4]     = __half2(__float2half_rn(k.x), __float2half_rn(k.y));
        *(__half2*)&sKhp[r * QKSTR + c4 + 2] = __half2(__float2half_rn(k.z), __float2half_rn(k.w));
        sVtp[(c4 + 0) * VTSTR + r] = __float2half_rn(v.x);
        sVtp[(c4 + 1) * VTSTR + r] = __float2half_rn(v.y);
        sVtp[(c4 + 2) * VTSTR + r] = __float2half_rn(v.z);
        sVtp[(c4 + 3) * VTSTR + r] = __float2half_rn(v.w);
    }
    __syncthreads();

    // ---- S = Q K^T : warp wid handles rows wm..wm+15, all 128 cols ----
    const int wm = wid * 16;
    float acc[16][4];
#pragma unroll
    for (int nf = 0; nf < 16; nf++)
#pragma unroll
        for (int r = 0; r < 4; r++) acc[nf][r] = 0.f;

#pragma unroll
    for (int kk = 0; kk < 2; kk++) {
        const int kb0 = kk * 16;
        const uint32_t aoff = (uint32_t)(((wm + a_row) * QKSTR) + kb0 + a_col) * 2;
        uint32_t ah[4], al[4];
        ldsm_x4(ah, sQh + aoff);
        ldsm_x4(al, sQl + aoff);
#pragma unroll
        for (int j = 0; j < 8; j++) {         // nf pairs (2j, 2j+1)
            uint32_t bf[4];
            ldsm_x4(bf, sKh + (uint32_t)((((2 * j + b_nf) * 8 + b_row) * QKSTR) + kb0 + b_col) * 2);
            mma16816(acc[2 * j],     ah, bf);
            mma16816(acc[2 * j],     al, bf);
            mma16816(acc[2 * j + 1], ah, bf + 2);
            mma16816(acc[2 * j + 1], al, bf + 2);
        }
    }

    // ---- softmax in registers ----
    float mx0 = -1e30f, mx1 = -1e30f;
#pragma unroll
    for (int nf = 0; nf < 16; nf++) {
        mx0 = fmaxf(mx0, fmaxf(acc[nf][0], acc[nf][1]));
        mx1 = fmaxf(mx1, fmaxf(acc[nf][2], acc[nf][3]));
    }
#pragma unroll
    for (int o = 2; o >= 1; o >>= 1) {
        mx0 = fmaxf(mx0, __shfl_xor_sync(0xffffffffu, mx0, o));
        mx1 = fmaxf(mx1, __shfl_xor_sync(0xffffffffu, mx1, o));
    }
    float s0 = 0.f, s1 = 0.f;
#pragma unroll
    for (int nf = 0; nf < 16; nf++) {
        acc[nf][0] = __expf(acc[nf][0] - mx0);
        acc[nf][1] = __expf(acc[nf][1] - mx0);
        acc[nf][2] = __expf(acc[nf][2] - mx1);
        acc[nf][3] = __expf(acc[nf][3] - mx1);
        s0 += acc[nf][0] + acc[nf][1];
        s1 += acc[nf][2] + acc[nf][3];
    }
#pragma unroll
    for (int o = 2; o >= 1; o >>= 1) {
        s0 += __shfl_xor_sync(0xffffffffu, s0, o);
        s1 += __shfl_xor_sync(0xffffffffu, s1, o);
    }
    const float inv0 = 1.0f / s0;
    const float inv1 = 1.0f / s1;

    // ---- pack P into A-fragments (hi/lo), consuming acc ----
    uint32_t ph[8][4], pl[8][4];
#pragma unroll
    for (int j = 0; j < 8; j++) {
        float p00 = acc[2 * j][0] * inv0,     p01 = acc[2 * j][1] * inv0;
        float p02 = acc[2 * j][2] * inv1,     p03 = acc[2 * j][3] * inv1;
        float p10 = acc[2 * j + 1][0] * inv0, p11 = acc[2 * j + 1][1] * inv0;
        float p12 = acc[2 * j + 1][2] * inv1, p13 = acc[2 * j + 1][3] * inv1;
        __half ha, la, hb, lb;
        split_half(p00, ha, la); split_half(p01, hb, lb);
        ph[j][0] = pack2h(ha, hb); pl[j][0] = pack2h(la, lb);
        split_half(p02, ha, la); split_half(p03, hb, lb);
        ph[j][1] = pack2h(ha, hb); pl[j][1] = pack2h(la, lb);
        split_half(p10, ha, la); split_half(p11, hb, lb);
        ph[j][2] = pack2h(ha, hb); pl[j][2] = pack2h(la, lb);
        split_half(p12, ha, la); split_half(p13, hb, lb);
        ph[j][3] = pack2h(ha, hb); pl[j][3] = pack2h(la, lb);
    }

    // ---- O = P V : warp tile m16 x n32, k=128 (8 k16 blocks) ----
    float o[4][4];
#pragma unroll
    for (int nf = 0; nf < 4; nf++)
#pragma unroll
        for (int r = 0; r < 4; r++) o[nf][r] = 0.f;

#pragma unroll
    for (int kk = 0; kk < 8; kk++) {
        const int kb0 = kk * 16;
        uint32_t b01[4], b23[4];
        ldsm_x4(b01, sVt + (uint32_t)(((b_nf * 8 + b_row) * VTSTR) + kb0 + b_col) * 2);
        ldsm_x4(b23, sVt + (uint32_t)((((2 + b_nf) * 8 + b_row) * VTSTR) + kb0 + b_col) * 2);
#pragma unroll
        for (int nf = 0; nf < 4; nf++) {
            const uint32_t* bp = (nf < 2) ? (b01 + (nf & 1) * 2) : (b23 + (nf & 1) * 2);
            mma16816(o[nf], ph[kk], bp);
            mma16816(o[nf], pl[kk], bp);
        }
    }

    // ---- epilogue: + residual, ReLU, store ----
    const size_t orowbase = (size_t)(b * FDIM);
#pragma unroll
    for (int nf = 0; nf < 4; nf++) {
        int cc = nf * 8 + tig * 2;
        int r0 = wm + grp;
        int r1 = r0 + 8;
        float2 rr0 = *(const float2*)&g_qkvr[rowbase + (size_t)r0 * NCOLS + 768 + colQ + cc];
        float2 rr1 = *(const float2*)&g_qkvr[rowbase + (size_t)r1 * NCOLS + 768 + colQ + cc];
        float2 o0, o1;
        o0.x = fmaxf(o[nf][0] + rr0.x, 0.f);
        o0.y = fmaxf(o[nf][1] + rr0.y, 0.f);
        o1.x = fmaxf(o[nf][2] + rr1.x, 0.f);
        o1.y = fmaxf(o[nf][3] + rr1.y, 0.f);
        *(float2*)&out[(orowbase + r0) * EDIM + colQ + cc] = o0;
        *(float2*)&out[(orowbase + r1) * EDIM + colQ + cc] = o1;
    }
}

// ---------------------------------------------------------------------------
// Launch
// ---------------------------------------------------------------------------
extern "C" void kernel_launch(void* const* d_in, const int* in_sizes, int n_in,
                              void* d_out, int out_size)
{
    const float* inputs = (const float*)d_in[0];
    const float* Wq     = (const float*)d_in[1];
    const float* Wk     = (const float*)d_in[2];
    const float* Wv     = (const float*)d_in[3];
    const float* Wr     = (const float*)d_in[4];
    float* out = (float*)d_out;

    cudaFuncSetAttribute(proj_mma_kernel, cudaFuncAttributeMaxDynamicSharedMemorySize,
                         PROJ_SMEM_BYTES);
    cudaFuncSetAttribute(attn_mma_kernel, cudaFuncAttributeMaxDynamicSharedMemorySize,
                         ATT_SMEM_BYTES);

    convert_A_kernel<<<(MROWS * EDIM / 4 + 255) / 256, 256>>>(inputs);
    convert_W_kernel<<<(NCOLS * EDIM + 255) / 256, 256>>>(Wq, Wk, Wv, Wr);

    dim3 gridP(NCOLS / 128, MROWS / 128);   // 8 x 1024
    proj_mma_kernel<<<gridP, 256, PROJ_SMEM_BYTES>>>();

    attn_mma_kernel<<<BATCH * HEADS, 256, ATT_SMEM_BYTES>>>(out);
}